// round 12
// baseline (speedup 1.0000x reference)
#include <cuda_runtime.h>
#include <cuda_bf16.h>
#include <mma.h>
#include <cstdint>

using namespace nvcuda;

#define NN 50000
#define NPAD 50048            // multiple of 64
#define EE 800000
#define NFEAT 256
#define NHID 32
#define NHEADS 4
#define HIDALL 128
#define CAP 96
#define LRELU_ALPHA 0.2f

// ---------------- scratch (static device globals; no allocation) -------------
__device__ __align__(16) float g_h1[NPAD * HIDALL];
__device__ __align__(16) float g_h2[NPAD * NHID];
__device__ __align__(16) float g_s1[NN * NHEADS];
__device__ __align__(16) float g_s2[NN * NHEADS];
__device__ float g_s1o[NN];
__device__ float g_s2o[NN];
__device__ int   g_cnt[NN];
__device__ int   g_bucket[NN * CAP];
__device__ __align__(16) __nv_bfloat16 g_wthi[HIDALL * NFEAT];   // Wt[n][k]
__device__ __align__(16) __nv_bfloat16 g_wtlo[HIDALL * NFEAT];
__device__ __align__(16) __nv_bfloat16 g_wohi[HIDALL * NHID];    // Wo[k][j]
__device__ __align__(16) __nv_bfloat16 g_wolo[HIDALL * NHID];
__device__ __align__(16) __nv_bfloat16 g_hp1hi[NPAD * HIDALL];   // zero-init pads
__device__ __align__(16) __nv_bfloat16 g_hp1lo[NPAD * HIDALL];

// ---------------- cp.async helpers -------------------------------------------
__device__ __forceinline__ uint32_t smem_u32(const void* p) {
    uint32_t a;
    asm("{ .reg .u64 t; cvta.to.shared.u64 t, %1; cvt.u32.u64 %0, t; }" : "=r"(a) : "l"(p));
    return a;
}
#define CP_ASYNC16(dst, src) \
    asm volatile("cp.async.ca.shared.global [%0], [%1], 16;" :: "r"(dst), "l"(src))
#define CP_COMMIT()  asm volatile("cp.async.commit_group;" ::: "memory")
#define CP_WAIT0()   asm volatile("cp.async.wait_group 0;" ::: "memory")

// ---------------- prep: zero counters + weight hi/lo conversion ---------------
__global__ void prep_kernel(const float* __restrict__ Ws, const float* __restrict__ Wo) {
    int t = blockIdx.x * blockDim.x + threadIdx.x;
    if (t < NN) g_cnt[t] = 0;
    if (t < HIDALL * NFEAT) {                  // Wt[n=128][k=256]
        int n = t / NFEAT, k = t % NFEAT;
        float v = Ws[(n >> 5) * (NFEAT * NHID) + k * NHID + (n & 31)];
        __nv_bfloat16 h = __float2bfloat16(v);
        g_wthi[t] = h;
        g_wtlo[t] = __float2bfloat16(v - __bfloat162float(h));
    }
    if (t < HIDALL * NHID) {                   // Wo[k=128][j=32]
        float v = Wo[t];
        __nv_bfloat16 h = __float2bfloat16(v);
        g_wohi[t] = h;
        g_wolo[t] = __float2bfloat16(v - __bfloat162float(h));
    }
}

__global__ void scatter_kernel(const int* __restrict__ src, const int* __restrict__ dst) {
    int e = blockIdx.x * blockDim.x + threadIdx.x;
    if (e < EE) {
        int s = src[e];
        int p = atomicAdd(&g_cnt[s], 1);
        if (p < CAP) g_bucket[s * CAP + p] = dst[e];
    }
}

// ---------------- GEMM1: 64x128 tile, 8 warps, 2 blocks/SM, async staged -----
// Same R9 pipeline (cp.async fp32 A ping-pong -> smem convert -> MMA), halved
// tile height so two independent blocks per SM overlap barrier/convert phases.
#define LDA32 36
#define LDT 40
#define OFF_F32A 0                    // 2 x 64*36 fp32 = 18432 B
#define OFF_ABF  18432                // hi 5120 + lo 5120 = 10240 B
#define OFF_BBF  28672                // 2 buf x (hi 10240 + lo 10240) = 40960 B
#define OFF_ASS  69632                // 256 floats = 1024 B
#define G1_SMEM  70656

__global__ void __launch_bounds__(256, 2) gemm1_wmma_kernel(const float* __restrict__ x,
                                                            const float* __restrict__ Aatt) {
    extern __shared__ __align__(16) char SM[];
    float* F32A = (float*)(SM + OFF_F32A);
    __nv_bfloat16* ABF = (__nv_bfloat16*)(SM + OFF_ABF);
    __nv_bfloat16* BBF = (__nv_bfloat16*)(SM + OFF_BBF);
    float* AsS = (float*)(SM + OFF_ASS);

    const int tid = threadIdx.x;
    const int warp = tid >> 5;         // 0..7
    const int lane = tid & 31;
    const int wr = warp >> 2;          // 0..1
    const int wc = warp & 3;           // 0..3
    const int row0 = blockIdx.x * 64;
    const int wrow = wr * 32;
    const int wcol = wc * 32;

    if (tid < NHEADS * 2 * NHID) AsS[tid] = Aatt[tid];

    const int sa_row = tid >> 2;       // 0..63 (conversion: 4 threads/row)
    const int sa_qq = tid & 3;

    wmma::fragment<wmma::accumulator, 16, 16, 16, float> acc[2][2];
#pragma unroll
    for (int i = 0; i < 2; i++)
#pragma unroll
        for (int j = 0; j < 2; j++) wmma::fill_fragment(acc[i][j], 0.f);

    // ---- stage chunk 0 ----
    {
        const int k0 = 0;
        uint32_t f32a = smem_u32(F32A);
        uint32_t bhi = smem_u32(BBF);
        uint32_t blo = smem_u32(BBF + 5120);
#pragma unroll
        for (int it = 0; it < 2; it++) {     // B: 512 cps each half
            int idx = it * 256 + tid;
            int n = idx >> 2, q = idx & 3;
            CP_ASYNC16(bhi + (n * LDT + q * 8) * 2, g_wthi + (long)n * NFEAT + k0 + q * 8);
            CP_ASYNC16(blo + (n * LDT + q * 8) * 2, g_wtlo + (long)n * NFEAT + k0 + q * 8);
        }
#pragma unroll
        for (int it = 0; it < 2; it++) {     // A: 512 float4
            int idx = it * 256 + tid;
            int row = idx >> 3, q = idx & 7;
            int grow = row0 + row;
            if (grow < NN) {
                CP_ASYNC16(f32a + (row * LDA32 + q * 4) * 4, x + (long)grow * NFEAT + k0 + q * 4);
            } else {
                *(float4*)(F32A + row * LDA32 + q * 4) = make_float4(0.f, 0.f, 0.f, 0.f);
            }
        }
        CP_COMMIT();
        CP_WAIT0();
        __syncthreads();
    }

#pragma unroll 1
    for (int c = 0; c < 8; c++) {
        const int cur = c & 1, nxt = cur ^ 1;

        if (c < 7) {
            const int k1 = (c + 1) * 32;
            uint32_t f32a = smem_u32(F32A + nxt * (64 * LDA32));
            uint32_t bhi = smem_u32(BBF + nxt * 10240);
            uint32_t blo = smem_u32(BBF + nxt * 10240 + 5120);
#pragma unroll
            for (int it = 0; it < 2; it++) {
                int idx = it * 256 + tid;
                int n = idx >> 2, q = idx & 3;
                CP_ASYNC16(bhi + (n * LDT + q * 8) * 2, g_wthi + (long)n * NFEAT + k1 + q * 8);
                CP_ASYNC16(blo + (n * LDT + q * 8) * 2, g_wtlo + (long)n * NFEAT + k1 + q * 8);
            }
#pragma unroll
            for (int it = 0; it < 2; it++) {
                int idx = it * 256 + tid;
                int row = idx >> 3, q = idx & 7;
                int grow = row0 + row;
                if (grow < NN) {
                    CP_ASYNC16(f32a + (row * LDA32 + q * 4) * 4, x + (long)grow * NFEAT + k1 + q * 4);
                } else {
                    *(float4*)(F32A + nxt * (64 * LDA32) + row * LDA32 + q * 4) =
                        make_float4(0.f, 0.f, 0.f, 0.f);
                }
            }
            CP_COMMIT();
        }

        // convert current fp32 chunk -> bf16 hi/lo work buffer (smem->smem)
        {
            const float* src = F32A + cur * (64 * LDA32) + sa_row * LDA32;
            __nv_bfloat16* dhi = ABF + sa_row * LDT;
            __nv_bfloat16* dlo = ABF + 2560 + sa_row * LDT;
#pragma unroll
            for (int h = 0; h < 2; h++) {
                int q = sa_qq * 2 + h;
                float4 v = *(const float4*)(src + q * 4);
                __nv_bfloat16 h0 = __float2bfloat16(v.x), h1 = __float2bfloat16(v.y);
                __nv_bfloat16 h2 = __float2bfloat16(v.z), h3 = __float2bfloat16(v.w);
                __nv_bfloat162* ph = (__nv_bfloat162*)(dhi + q * 4);
                __nv_bfloat162* pl = (__nv_bfloat162*)(dlo + q * 4);
                ph[0] = __nv_bfloat162(h0, h1); ph[1] = __nv_bfloat162(h2, h3);
                pl[0] = __nv_bfloat162(__float2bfloat16(v.x - __bfloat162float(h0)),
                                       __float2bfloat16(v.y - __bfloat162float(h1)));
                pl[1] = __nv_bfloat162(__float2bfloat16(v.z - __bfloat162float(h2)),
                                       __float2bfloat16(v.w - __bfloat162float(h3)));
            }
        }
        __syncthreads();

        // MMAs for chunk c
        __nv_bfloat16* AsHi = ABF;
        __nv_bfloat16* AsLo = ABF + 2560;
        __nv_bfloat16* BsHi = BBF + cur * 10240;
        __nv_bfloat16* BsLo = BBF + cur * 10240 + 5120;
#pragma unroll
        for (int kk = 0; kk < 32; kk += 16) {
            wmma::fragment<wmma::matrix_a, 16, 16, 16, __nv_bfloat16, wmma::row_major> ahi[2], alo[2];
#pragma unroll
            for (int i = 0; i < 2; i++) {
                wmma::load_matrix_sync(ahi[i], AsHi + (wrow + 16 * i) * LDT + kk, LDT);
                wmma::load_matrix_sync(alo[i], AsLo + (wrow + 16 * i) * LDT + kk, LDT);
            }
#pragma unroll
            for (int j = 0; j < 2; j++) {
                wmma::fragment<wmma::matrix_b, 16, 16, 16, __nv_bfloat16, wmma::col_major> bhi, blo;
                wmma::load_matrix_sync(bhi, BsHi + (wcol + 16 * j) * LDT + kk, LDT);
                wmma::load_matrix_sync(blo, BsLo + (wcol + 16 * j) * LDT + kk, LDT);
#pragma unroll
                for (int i = 0; i < 2; i++) {
                    wmma::mma_sync(acc[i][j], ahi[i], bhi, acc[i][j]);
                    wmma::mma_sync(acc[i][j], alo[i], bhi, acc[i][j]);
                    wmma::mma_sync(acc[i][j], ahi[i], blo, acc[i][j]);
                }
            }
        }

        if (c < 7) CP_WAIT0();
        __syncthreads();
    }

#pragma unroll
    for (int i = 0; i < 2; i++)
#pragma unroll
        for (int j = 0; j < 2; j++)
            wmma::store_matrix_sync(g_h1 + (long)(row0 + wrow + 16 * i) * HIDALL + wcol + 16 * j,
                                    acc[i][j], HIDALL, wmma::mem_row_major);
    __syncthreads();

    // fused s1/s2: 256 (row,head) tasks over 8 warps
    for (int t = warp; t < 256; t += 8) {
        int r = t >> 2, head = t & 3;
        int grow = row0 + r;
        if (grow < NN) {
            float v = g_h1[(long)grow * HIDALL + head * 32 + lane];
            float p = v * AsS[head * 64 + lane];
            float q = v * AsS[head * 64 + 32 + lane];
#pragma unroll
            for (int off = 16; off; off >>= 1) {
                p += __shfl_xor_sync(0xffffffffu, p, off);
                q += __shfl_xor_sync(0xffffffffu, q, off);
            }
            if (lane == 0) {
                g_s1[grow * 4 + head] = p;
                g_s2[grow * 4 + head] = q;
            }
        }
    }
}

// ---------------- layer-1 aggregation (R7 verbatim): warp per node -----------
__global__ void __launch_bounds__(256) agg4_kernel() {
    const int wid = threadIdx.x >> 5;
    const int lane = threadIdx.x & 31;
    int node = blockIdx.x * 8 + wid;
    if (node >= NN) return;
    int cnt = min(g_cnt[node], CAP);
    int base = node * CAP;
    int hsel = lane >> 3;
    float s1h = g_s1[node * 4 + hsel];

    float4 acc = make_float4(0.f, 0.f, 0.f, 0.f);
    float dsum = 0.f;

    auto proc = [&](int d) {
        float e = s1h + __ldg(g_s2 + d * 4 + hsel);
        e = e > 0.f ? e : LRELU_ALPHA * e;
        float w = __expf(e);
        dsum += w;
        float4 hv = *(const float4*)(g_h1 + (long)d * HIDALL + lane * 4);
        acc.x += w * hv.x; acc.y += w * hv.y;
        acc.z += w * hv.z; acc.w += w * hv.w;
    };

    int i = 0;
    for (; i + 4 <= cnt; i += 4) {
        int4 dd = *(const int4*)(g_bucket + base + i);
        proc(dd.x); proc(dd.y); proc(dd.z); proc(dd.w);
    }
    for (; i < cnt; ++i) proc(g_bucket[base + i]);

    float inv = dsum > 0.f ? __fdividef(1.f, dsum) : 0.f;
    acc.x *= inv; acc.y *= inv; acc.z *= inv; acc.w *= inv;
    acc.x = acc.x > 0.f ? acc.x : (__expf(acc.x) - 1.f);
    acc.y = acc.y > 0.f ? acc.y : (__expf(acc.y) - 1.f);
    acc.z = acc.z > 0.f ? acc.z : (__expf(acc.z) - 1.f);
    acc.w = acc.w > 0.f ? acc.w : (__expf(acc.w) - 1.f);

    __nv_bfloat16 h0 = __float2bfloat16(acc.x), h1 = __float2bfloat16(acc.y);
    __nv_bfloat16 h2 = __float2bfloat16(acc.z), h3 = __float2bfloat16(acc.w);
    __nv_bfloat162* ph = (__nv_bfloat162*)(g_hp1hi + (long)node * HIDALL + lane * 4);
    __nv_bfloat162* pl = (__nv_bfloat162*)(g_hp1lo + (long)node * HIDALL + lane * 4);
    ph[0] = __nv_bfloat162(h0, h1); ph[1] = __nv_bfloat162(h2, h3);
    pl[0] = __nv_bfloat162(__float2bfloat16(acc.x - __bfloat162float(h0)),
                           __float2bfloat16(acc.y - __bfloat162float(h1)));
    pl[1] = __nv_bfloat162(__float2bfloat16(acc.z - __bfloat162float(h2)),
                           __float2bfloat16(acc.w - __bfloat162float(h3)));
}

// ---------------- GEMM2 (R8 verbatim): global-frag wmma + fused s1o/s2o ------
__global__ void __launch_bounds__(256) gemm2_wmma_kernel(const float* __restrict__ Ao) {
    __shared__ float AoS[2 * NHID];
    __shared__ float h2buf[8][16 * NHID];
    if (threadIdx.x < 2 * NHID) AoS[threadIdx.x] = Ao[threadIdx.x];
    __syncthreads();

    const int warp = threadIdx.x >> 5;
    const int lane = threadIdx.x & 31;
    const int row0 = blockIdx.x * 128 + warp * 16;

    wmma::fragment<wmma::accumulator, 16, 16, 16, float> acc[2];
    wmma::fill_fragment(acc[0], 0.f);
    wmma::fill_fragment(acc[1], 0.f);

#pragma unroll
    for (int k0 = 0; k0 < HIDALL; k0 += 16) {
        wmma::fragment<wmma::matrix_a, 16, 16, 16, __nv_bfloat16, wmma::row_major> ahi, alo;
        wmma::load_matrix_sync(ahi, g_hp1hi + (long)row0 * HIDALL + k0, HIDALL);
        wmma::load_matrix_sync(alo, g_hp1lo + (long)row0 * HIDALL + k0, HIDALL);
#pragma unroll
        for (int j = 0; j < 2; j++) {
            wmma::fragment<wmma::matrix_b, 16, 16, 16, __nv_bfloat16, wmma::row_major> bhi, blo;
            wmma::load_matrix_sync(bhi, g_wohi + k0 * NHID + j * 16, NHID);
            wmma::load_matrix_sync(blo, g_wolo + k0 * NHID + j * 16, NHID);
            wmma::mma_sync(acc[j], ahi, bhi, acc[j]);
            wmma::mma_sync(acc[j], alo, bhi, acc[j]);
            wmma::mma_sync(acc[j], ahi, blo, acc[j]);
        }
    }
    wmma::store_matrix_sync(&h2buf[warp][0], acc[0], NHID, wmma::mem_row_major);
    wmma::store_matrix_sync(&h2buf[warp][16], acc[1], NHID, wmma::mem_row_major);
    __syncwarp();

    const float ao1 = AoS[lane], ao2 = AoS[32 + lane];
#pragma unroll
    for (int r = 0; r < 16; r++) {
        int grow = row0 + r;
        float v = h2buf[warp][r * NHID + lane];
        g_h2[(long)grow * NHID + lane] = v;
        if (grow < NN) {
            float p = v * ao1, q = v * ao2;
#pragma unroll
            for (int off = 16; off; off >>= 1) {
                p += __shfl_xor_sync(0xffffffffu, p, off);
                q += __shfl_xor_sync(0xffffffffu, q, off);
            }
            if (lane == 0) {
                g_s1o[grow] = p;
                g_s2o[grow] = q;
            }
        }
    }
}

// ---------------- layer-2 aggregation (R7 verbatim): warp per node -----------
__global__ void __launch_bounds__(256) agg1_kernel(float* __restrict__ hout) {
    int node = blockIdx.x * 8 + (threadIdx.x >> 5);
    int lane = threadIdx.x & 31;
    if (node >= NN) return;
    int cnt = min(g_cnt[node], CAP);
    int base = node * CAP;
    float s1v = g_s1o[node];

    float acc = 0.f, dsum = 0.f;
    auto proc = [&](int d) {
        float e = s1v + __ldg(g_s2o + d);
        e = e > 0.f ? e : LRELU_ALPHA * e;
        float w = __expf(e);
        dsum += w;
        acc += w * __ldg(g_h2 + (long)d * NHID + lane);
    };
    int i = 0;
    for (; i + 4 <= cnt; i += 4) {
        int4 dd = *(const int4*)(g_bucket + base + i);
        proc(dd.x); proc(dd.y); proc(dd.z); proc(dd.w);
    }
    for (; i < cnt; ++i) proc(g_bucket[base + i]);

    float inv = dsum > 0.f ? __fdividef(1.f, dsum) : 0.f;
    acc *= inv;
    acc = acc > 0.f ? acc : (__expf(acc) - 1.f);
    hout[(long)node * NHID + lane] = acc;
}

// ---------------- launch -----------------------------------------------------
extern "C" void kernel_launch(void* const* d_in, const int* in_sizes, int n_in,
                              void* d_out, int out_size) {
    const float* x   = (const float*)d_in[0];
    const int*   src = (const int*)d_in[1];
    const int*   dst = (const int*)d_in[2];
    const float* Ws  = (const float*)d_in[3];
    const float* As  = (const float*)d_in[4];
    const float* Wo  = (const float*)d_in[5];
    const float* Ao  = (const float*)d_in[6];
    float* out = (float*)d_out;

    cudaFuncSetAttribute(gemm1_wmma_kernel, cudaFuncAttributeMaxDynamicSharedMemorySize, G1_SMEM);

    prep_kernel<<<(NN + 255) / 256, 256>>>(Ws, Wo);
    scatter_kernel<<<(EE + 255) / 256, 256>>>(src, dst);

    gemm1_wmma_kernel<<<NPAD / 64, 256, G1_SMEM>>>(x, As);
    agg4_kernel<<<(NN + 7) / 8, 256>>>();
    gemm2_wmma_kernel<<<NPAD / 128, 256>>>(Ao);
    agg1_kernel<<<(NN + 7) / 8, 256>>>(out);
}

// round 13
// speedup vs baseline: 1.0317x; 1.0317x over previous
#include <cuda_runtime.h>
#include <cuda_bf16.h>
#include <mma.h>
#include <cstdint>

using namespace nvcuda;

#define NN 50000
#define NPAD 50048            // multiple of 128
#define EE 800000
#define NFEAT 256
#define NHID 32
#define NHEADS 4
#define HIDALL 128
#define CAP 96
#define LRELU_ALPHA 0.2f

// ---------------- scratch (static device globals; no allocation) -------------
__device__ __align__(16) float g_h1[NPAD * HIDALL];
__device__ __align__(16) float g_h2[NPAD * NHID];
__device__ __align__(16) float g_s1[NN * NHEADS];
__device__ __align__(16) float g_s2[NN * NHEADS];
__device__ float g_s1o[NN];
__device__ float g_s2o[NN];
__device__ int   g_cnt[NN];
__device__ int   g_bucket[NN * CAP];
__device__ __align__(16) __nv_bfloat16 g_wthi[HIDALL * NFEAT];   // Wt[n][k]
__device__ __align__(16) __nv_bfloat16 g_wtlo[HIDALL * NFEAT];
__device__ __align__(16) __nv_bfloat16 g_wohi[HIDALL * NHID];    // Wo[k][j]
__device__ __align__(16) __nv_bfloat16 g_wolo[HIDALL * NHID];
__device__ __align__(16) __nv_bfloat16 g_hp1hi[NPAD * HIDALL];   // zero-init pads
__device__ __align__(16) __nv_bfloat16 g_hp1lo[NPAD * HIDALL];

// ---------------- cp.async helpers -------------------------------------------
__device__ __forceinline__ uint32_t smem_u32(const void* p) {
    uint32_t a;
    asm("{ .reg .u64 t; cvta.to.shared.u64 t, %1; cvt.u32.u64 %0, t; }" : "=r"(a) : "l"(p));
    return a;
}
#define CP_ASYNC16(dst, src) \
    asm volatile("cp.async.ca.shared.global [%0], [%1], 16;" :: "r"(dst), "l"(src))
#define CP_COMMIT()  asm volatile("cp.async.commit_group;" ::: "memory")
#define CP_WAIT0()   asm volatile("cp.async.wait_group 0;" ::: "memory")

// ---------------- prep: zero counters + weight hi/lo conversion ---------------
__global__ void prep_kernel(const float* __restrict__ Ws, const float* __restrict__ Wo) {
    int t = blockIdx.x * blockDim.x + threadIdx.x;
    if (t < NN) g_cnt[t] = 0;
    if (t < HIDALL * NFEAT) {                  // Wt[n=128][k=256]
        int n = t / NFEAT, k = t % NFEAT;
        float v = Ws[(n >> 5) * (NFEAT * NHID) + k * NHID + (n & 31)];
        __nv_bfloat16 h = __float2bfloat16(v);
        g_wthi[t] = h;
        g_wtlo[t] = __float2bfloat16(v - __bfloat162float(h));
    }
    if (t < HIDALL * NHID) {                   // Wo[k=128][j=32]
        float v = Wo[t];
        __nv_bfloat16 h = __float2bfloat16(v);
        g_wohi[t] = h;
        g_wolo[t] = __float2bfloat16(v - __bfloat162float(h));
    }
}

__global__ void scatter_kernel(const int* __restrict__ src, const int* __restrict__ dst) {
    int e = blockIdx.x * blockDim.x + threadIdx.x;
    if (e < EE) {
        int s = src[e];
        int p = atomicAdd(&g_cnt[s], 1);
        if (p < CAP) g_bucket[s * CAP + p] = dst[e];
    }
}

// ---------------- GEMM1 (R9 verbatim): async-staged wmma, 512 thr ------------
#define LDA32 36
#define LDT 40
#define OFF_F32A 0
#define OFF_ABF  36864
#define OFF_BBF  57344
#define OFF_ASS  98304
#define G1_SMEM  99328

__global__ void __launch_bounds__(512) gemm1_wmma_kernel(const float* __restrict__ x,
                                                         const float* __restrict__ Aatt) {
    extern __shared__ __align__(16) char SM[];
    float* F32A = (float*)(SM + OFF_F32A);
    __nv_bfloat16* ABF = (__nv_bfloat16*)(SM + OFF_ABF);
    __nv_bfloat16* BBF = (__nv_bfloat16*)(SM + OFF_BBF);
    float* AsS = (float*)(SM + OFF_ASS);

    const int tid = threadIdx.x;
    const int warp = tid >> 5;
    const int lane = tid & 31;
    const int wr = warp >> 2;
    const int wc = warp & 3;
    const int row0 = blockIdx.x * 128;
    const int wrow = wr * 32;
    const int wcol = wc * 32;

    if (tid < NHEADS * 2 * NHID) AsS[tid] = Aatt[tid];

    const int sa_row = tid >> 2;
    const int sa_qq = tid & 3;
    const int sb_n = tid >> 2, sb_q = tid & 3;

    wmma::fragment<wmma::accumulator, 16, 16, 16, float> acc[2][2];
#pragma unroll
    for (int i = 0; i < 2; i++)
#pragma unroll
        for (int j = 0; j < 2; j++) wmma::fill_fragment(acc[i][j], 0.f);

    {
        const int k0 = 0;
        uint32_t f32a = smem_u32(F32A);
        uint32_t bhi = smem_u32(BBF);
        uint32_t blo = smem_u32(BBF + 5120);
        CP_ASYNC16(bhi + (sb_n * LDT + sb_q * 8) * 2, g_wthi + (long)sb_n * NFEAT + k0 + sb_q * 8);
        CP_ASYNC16(blo + (sb_n * LDT + sb_q * 8) * 2, g_wtlo + (long)sb_n * NFEAT + k0 + sb_q * 8);
#pragma unroll
        for (int it = 0; it < 2; it++) {
            int idx = it * 512 + tid;
            int row = idx >> 3, q = idx & 7;
            int grow = row0 + row;
            if (grow < NN) {
                CP_ASYNC16(f32a + (row * LDA32 + q * 4) * 4, x + (long)grow * NFEAT + k0 + q * 4);
            } else {
                *(float4*)(F32A + row * LDA32 + q * 4) = make_float4(0.f, 0.f, 0.f, 0.f);
            }
        }
        CP_COMMIT();
        CP_WAIT0();
        __syncthreads();
    }

#pragma unroll 1
    for (int c = 0; c < 8; c++) {
        const int cur = c & 1, nxt = cur ^ 1;

        if (c < 7) {
            const int k1 = (c + 1) * 32;
            uint32_t f32a = smem_u32(F32A + nxt * (128 * LDA32));
            uint32_t bhi = smem_u32(BBF + nxt * 10240);
            uint32_t blo = smem_u32(BBF + nxt * 10240 + 5120);
            CP_ASYNC16(bhi + (sb_n * LDT + sb_q * 8) * 2, g_wthi + (long)sb_n * NFEAT + k1 + sb_q * 8);
            CP_ASYNC16(blo + (sb_n * LDT + sb_q * 8) * 2, g_wtlo + (long)sb_n * NFEAT + k1 + sb_q * 8);
#pragma unroll
            for (int it = 0; it < 2; it++) {
                int idx = it * 512 + tid;
                int row = idx >> 3, q = idx & 7;
                int grow = row0 + row;
                if (grow < NN) {
                    CP_ASYNC16(f32a + (row * LDA32 + q * 4) * 4, x + (long)grow * NFEAT + k1 + q * 4);
                } else {
                    *(float4*)(F32A + nxt * (128 * LDA32) + row * LDA32 + q * 4) =
                        make_float4(0.f, 0.f, 0.f, 0.f);
                }
            }
            CP_COMMIT();
        }

        {
            const float* src = F32A + cur * (128 * LDA32) + sa_row * LDA32;
            __nv_bfloat16* dhi = ABF + sa_row * LDT;
            __nv_bfloat16* dlo = ABF + 5120 + sa_row * LDT;
#pragma unroll
            for (int h = 0; h < 2; h++) {
                int q = sa_qq * 2 + h;
                float4 v = *(const float4*)(src + q * 4);
                __nv_bfloat16 h0 = __float2bfloat16(v.x), h1 = __float2bfloat16(v.y);
                __nv_bfloat16 h2 = __float2bfloat16(v.z), h3 = __float2bfloat16(v.w);
                __nv_bfloat162* ph = (__nv_bfloat162*)(dhi + q * 4);
                __nv_bfloat162* pl = (__nv_bfloat162*)(dlo + q * 4);
                ph[0] = __nv_bfloat162(h0, h1); ph[1] = __nv_bfloat162(h2, h3);
                pl[0] = __nv_bfloat162(__float2bfloat16(v.x - __bfloat162float(h0)),
                                       __float2bfloat16(v.y - __bfloat162float(h1)));
                pl[1] = __nv_bfloat162(__float2bfloat16(v.z - __bfloat162float(h2)),
                                       __float2bfloat16(v.w - __bfloat162float(h3)));
            }
        }
        __syncthreads();

        __nv_bfloat16* AsHi = ABF;
        __nv_bfloat16* AsLo = ABF + 5120;
        __nv_bfloat16* BsHi = BBF + cur * 10240;
        __nv_bfloat16* BsLo = BBF + cur * 10240 + 5120;
#pragma unroll
        for (int kk = 0; kk < 32; kk += 16) {
            wmma::fragment<wmma::matrix_a, 16, 16, 16, __nv_bfloat16, wmma::row_major> ahi[2], alo[2];
#pragma unroll
            for (int i = 0; i < 2; i++) {
                wmma::load_matrix_sync(ahi[i], AsHi + (wrow + 16 * i) * LDT + kk, LDT);
                wmma::load_matrix_sync(alo[i], AsLo + (wrow + 16 * i) * LDT + kk, LDT);
            }
#pragma unroll
            for (int j = 0; j < 2; j++) {
                wmma::fragment<wmma::matrix_b, 16, 16, 16, __nv_bfloat16, wmma::col_major> bhi, blo;
                wmma::load_matrix_sync(bhi, BsHi + (wcol + 16 * j) * LDT + kk, LDT);
                wmma::load_matrix_sync(blo, BsLo + (wcol + 16 * j) * LDT + kk, LDT);
#pragma unroll
                for (int i = 0; i < 2; i++) {
                    wmma::mma_sync(acc[i][j], ahi[i], bhi, acc[i][j]);
                    wmma::mma_sync(acc[i][j], alo[i], bhi, acc[i][j]);
                    wmma::mma_sync(acc[i][j], ahi[i], blo, acc[i][j]);
                }
            }
        }

        if (c < 7) CP_WAIT0();
        __syncthreads();
    }

#pragma unroll
    for (int i = 0; i < 2; i++)
#pragma unroll
        for (int j = 0; j < 2; j++)
            wmma::store_matrix_sync(g_h1 + (long)(row0 + wrow + 16 * i) * HIDALL + wcol + 16 * j,
                                    acc[i][j], HIDALL, wmma::mem_row_major);
    __syncthreads();

    for (int t = warp; t < 512; t += 16) {
        int r = t >> 2, head = t & 3;
        int grow = row0 + r;
        if (grow < NN) {
            float v = g_h1[(long)grow * HIDALL + head * 32 + lane];
            float p = v * AsS[head * 64 + lane];
            float q = v * AsS[head * 64 + 32 + lane];
#pragma unroll
            for (int off = 16; off; off >>= 1) {
                p += __shfl_xor_sync(0xffffffffu, p, off);
                q += __shfl_xor_sync(0xffffffffu, q, off);
            }
            if (lane == 0) {
                g_s1[grow * 4 + head] = p;
                g_s2[grow * 4 + head] = q;
            }
        }
    }
}

// ---------------- layer-1 aggregation (best measured): warp per node ---------
__global__ void __launch_bounds__(256) agg4_kernel() {
    const int wid = threadIdx.x >> 5;
    const int lane = threadIdx.x & 31;
    int node = blockIdx.x * 8 + wid;
    if (node >= NN) return;
    int cnt = min(g_cnt[node], CAP);
    int base = node * CAP;
    int hsel = lane >> 3;
    float s1h = g_s1[node * 4 + hsel];

    float4 acc = make_float4(0.f, 0.f, 0.f, 0.f);
    float dsum = 0.f;

    auto proc = [&](int d) {
        float e = s1h + __ldg(g_s2 + d * 4 + hsel);
        e = e > 0.f ? e : LRELU_ALPHA * e;
        float w = __expf(e);
        dsum += w;
        float4 hv = *(const float4*)(g_h1 + (long)d * HIDALL + lane * 4);
        acc.x += w * hv.x; acc.y += w * hv.y;
        acc.z += w * hv.z; acc.w += w * hv.w;
    };

    int i = 0;
    for (; i + 4 <= cnt; i += 4) {
        int4 dd = *(const int4*)(g_bucket + base + i);
        proc(dd.x); proc(dd.y); proc(dd.z); proc(dd.w);
    }
    for (; i < cnt; ++i) proc(g_bucket[base + i]);

    float inv = dsum > 0.f ? __fdividef(1.f, dsum) : 0.f;
    acc.x *= inv; acc.y *= inv; acc.z *= inv; acc.w *= inv;
    acc.x = acc.x > 0.f ? acc.x : (__expf(acc.x) - 1.f);
    acc.y = acc.y > 0.f ? acc.y : (__expf(acc.y) - 1.f);
    acc.z = acc.z > 0.f ? acc.z : (__expf(acc.z) - 1.f);
    acc.w = acc.w > 0.f ? acc.w : (__expf(acc.w) - 1.f);

    __nv_bfloat16 h0 = __float2bfloat16(acc.x), h1 = __float2bfloat16(acc.y);
    __nv_bfloat16 h2 = __float2bfloat16(acc.z), h3 = __float2bfloat16(acc.w);
    __nv_bfloat162* ph = (__nv_bfloat162*)(g_hp1hi + (long)node * HIDALL + lane * 4);
    __nv_bfloat162* pl = (__nv_bfloat162*)(g_hp1lo + (long)node * HIDALL + lane * 4);
    ph[0] = __nv_bfloat162(h0, h1); ph[1] = __nv_bfloat162(h2, h3);
    pl[0] = __nv_bfloat162(__float2bfloat16(acc.x - __bfloat162float(h0)),
                           __float2bfloat16(acc.y - __bfloat162float(h1)));
    pl[1] = __nv_bfloat162(__float2bfloat16(acc.z - __bfloat162float(h2)),
                           __float2bfloat16(acc.w - __bfloat162float(h3)));
}

// ---------------- GEMM2 (R8 verbatim): global-frag wmma + fused s1o/s2o ------
__global__ void __launch_bounds__(256) gemm2_wmma_kernel(const float* __restrict__ Ao) {
    __shared__ float AoS[2 * NHID];
    __shared__ float h2buf[8][16 * NHID];
    if (threadIdx.x < 2 * NHID) AoS[threadIdx.x] = Ao[threadIdx.x];
    __syncthreads();

    const int warp = threadIdx.x >> 5;
    const int lane = threadIdx.x & 31;
    const int row0 = blockIdx.x * 128 + warp * 16;

    wmma::fragment<wmma::accumulator, 16, 16, 16, float> acc[2];
    wmma::fill_fragment(acc[0], 0.f);
    wmma::fill_fragment(acc[1], 0.f);

#pragma unroll
    for (int k0 = 0; k0 < HIDALL; k0 += 16) {
        wmma::fragment<wmma::matrix_a, 16, 16, 16, __nv_bfloat16, wmma::row_major> ahi, alo;
        wmma::load_matrix_sync(ahi, g_hp1hi + (long)row0 * HIDALL + k0, HIDALL);
        wmma::load_matrix_sync(alo, g_hp1lo + (long)row0 * HIDALL + k0, HIDALL);
#pragma unroll
        for (int j = 0; j < 2; j++) {
            wmma::fragment<wmma::matrix_b, 16, 16, 16, __nv_bfloat16, wmma::row_major> bhi, blo;
            wmma::load_matrix_sync(bhi, g_wohi + k0 * NHID + j * 16, NHID);
            wmma::load_matrix_sync(blo, g_wolo + k0 * NHID + j * 16, NHID);
            wmma::mma_sync(acc[j], ahi, bhi, acc[j]);
            wmma::mma_sync(acc[j], alo, bhi, acc[j]);
            wmma::mma_sync(acc[j], ahi, blo, acc[j]);
        }
    }
    wmma::store_matrix_sync(&h2buf[warp][0], acc[0], NHID, wmma::mem_row_major);
    wmma::store_matrix_sync(&h2buf[warp][16], acc[1], NHID, wmma::mem_row_major);
    __syncwarp();

    const float ao1 = AoS[lane], ao2 = AoS[32 + lane];
#pragma unroll
    for (int r = 0; r < 16; r++) {
        int grow = row0 + r;
        float v = h2buf[warp][r * NHID + lane];
        g_h2[(long)grow * NHID + lane] = v;
        if (grow < NN) {
            float p = v * ao1, q = v * ao2;
#pragma unroll
            for (int off = 16; off; off >>= 1) {
                p += __shfl_xor_sync(0xffffffffu, p, off);
                q += __shfl_xor_sync(0xffffffffu, q, off);
            }
            if (lane == 0) {
                g_s1o[grow] = p;
                g_s2o[grow] = q;
            }
        }
    }
}

// ---------------- layer-2 aggregation (best measured): warp per node ---------
__global__ void __launch_bounds__(256) agg1_kernel(float* __restrict__ hout) {
    int node = blockIdx.x * 8 + (threadIdx.x >> 5);
    int lane = threadIdx.x & 31;
    if (node >= NN) return;
    int cnt = min(g_cnt[node], CAP);
    int base = node * CAP;
    float s1v = g_s1o[node];

    float acc = 0.f, dsum = 0.f;
    auto proc = [&](int d) {
        float e = s1v + __ldg(g_s2o + d);
        e = e > 0.f ? e : LRELU_ALPHA * e;
        float w = __expf(e);
        dsum += w;
        acc += w * __ldg(g_h2 + (long)d * NHID + lane);
    };
    int i = 0;
    for (; i + 4 <= cnt; i += 4) {
        int4 dd = *(const int4*)(g_bucket + base + i);
        proc(dd.x); proc(dd.y); proc(dd.z); proc(dd.w);
    }
    for (; i < cnt; ++i) proc(g_bucket[base + i]);

    float inv = dsum > 0.f ? __fdividef(1.f, dsum) : 0.f;
    acc *= inv;
    acc = acc > 0.f ? acc : (__expf(acc) - 1.f);
    hout[(long)node * NHID + lane] = acc;
}

// ---------------- launch -----------------------------------------------------
extern "C" void kernel_launch(void* const* d_in, const int* in_sizes, int n_in,
                              void* d_out, int out_size) {
    const float* x   = (const float*)d_in[0];
    const int*   src = (const int*)d_in[1];
    const int*   dst = (const int*)d_in[2];
    const float* Ws  = (const float*)d_in[3];
    const float* As  = (const float*)d_in[4];
    const float* Wo  = (const float*)d_in[5];
    const float* Ao  = (const float*)d_in[6];
    float* out = (float*)d_out;

    cudaFuncSetAttribute(gemm1_wmma_kernel, cudaFuncAttributeMaxDynamicSharedMemorySize, G1_SMEM);

    prep_kernel<<<(NN + 255) / 256, 256>>>(Ws, Wo);
    scatter_kernel<<<(EE + 255) / 256, 256>>>(src, dst);

    gemm1_wmma_kernel<<<NPAD / 128, 512, G1_SMEM>>>(x, As);
    agg4_kernel<<<(NN + 7) / 8, 256>>>();
    gemm2_wmma_kernel<<<NPAD / 128, 256>>>(Ao);
    agg1_kernel<<<(NN + 7) / 8, 256>>>(out);
}